// round 1
// baseline (speedup 1.0000x reference)
#include <cuda_runtime.h>
#include <cuda_bf16.h>

// LIFActivation: T=4 integrate-and-fire with subtractive reset, constant input.
// Elementwise: c = relu(x)/max(scale,1e-12); v=0; 4x { v+=c; if (v>=1) {v-=1; n+=1;} }
// out = (n/4) * max(scale,1e-12)
//
// Matches reference fp32 semantics bitwise:
//  - __fdiv_rn forces IEEE round-to-nearest division even under --use_fast_math
//  - sequential FADD accumulation + (v - 1 >= 0) test (identical sign to v >= 1
//    since v-1 is exact by Sterbenz for 0.5<=v<=2 and sign-correct elsewhere)
//  - n * (0.25f*s) == (n/4)*s exactly for n in {0..4}

__device__ __forceinline__ float lif_elem(float x, float s, float qs) {
    float c = __fdiv_rn(fmaxf(x, 0.0f), s);
    float v = 0.0f;
    float n = 0.0f;
#pragma unroll
    for (int t = 0; t < 4; ++t) {
        v += c;
        if (v >= 1.0f) {   // spike_fn(v - 1) == 1  <=>  v >= 1
            v -= 1.0f;
            n += 1.0f;
        }
    }
    return n * qs;
}

__global__ void __launch_bounds__(256)
lif_activation_kernel(const float4* __restrict__ x,
                      const float*  __restrict__ scale_ptr,
                      float4* __restrict__ out,
                      int n4) {
    int i = blockIdx.x * blockDim.x + threadIdx.x;
    if (i >= n4) return;

    float s  = fmaxf(__ldg(scale_ptr), 1e-12f);
    float qs = 0.25f * s;

    float4 xv = x[i];
    float4 r;
    r.x = lif_elem(xv.x, s, qs);
    r.y = lif_elem(xv.y, s, qs);
    r.z = lif_elem(xv.z, s, qs);
    r.w = lif_elem(xv.w, s, qs);
    out[i] = r;
}

extern "C" void kernel_launch(void* const* d_in, const int* in_sizes, int n_in,
                              void* d_out, int out_size) {
    const float* x     = (const float*)d_in[0];
    const float* scale = (const float*)d_in[1];
    float* out = (float*)d_out;

    int n  = out_size;          // 4096*8192, divisible by 4
    int n4 = n >> 2;

    const int threads = 256;
    int blocks = (n4 + threads - 1) / threads;
    lif_activation_kernel<<<blocks, threads>>>(
        (const float4*)x, scale, (float4*)out, n4);
}

// round 2
// speedup vs baseline: 1.4194x; 1.4194x over previous
#include <cuda_runtime.h>
#include <cuda_bf16.h>

// LIFActivation as a step function of x.
//
// Reference: c = RN(relu(x)/max(scale,1e-12)); 4-step IF with subtractive
// reset; out = (n_spikes/4)*scale. For a fixed positive scale, n_spikes is a
// monotone step function of the float x, with exactly four thresholds
// X1..X4 (n = #{k : x >= Xk}). A tiny setup kernel binary-searches each
// threshold over float bit-space, probing with the EXACT reference fp32
// sequence, so the main kernel's decisions match the reference bitwise.
// Output values V_k = RN(k * RN(0.25*s)) equal the reference's
// RN((k/4)*s) for k=0..4 (0.25*s is exact scaling; single rounding on the
// k=3 product either way).

__device__ float4 g_X;  // thresholds for n>=1..4
__device__ float4 g_V;  // output values for n=1..4

__device__ __forceinline__ int nspikes_ref(float x, float s) {
    float c = __fdiv_rn(fmaxf(x, 0.0f), s);  // IEEE RN div, exact ref semantics
    float v = 0.0f;
    int n = 0;
#pragma unroll
    for (int t = 0; t < 4; ++t) {
        v += c;
        if (v >= 1.0f) {  // H(v - 1) == 1  <=>  v >= 1
            v -= 1.0f;
            n += 1;
        }
    }
    return n;
}

__global__ void lif_setup_kernel(const float* __restrict__ scale_ptr) {
    int k = threadIdx.x;  // 0..3: threshold for n >= k+1
    if (k >= 4) return;
    float s = fmaxf(*scale_ptr, 1e-12f);
    int target = k + 1;

    // Smallest nonnegative float (by bit pattern == by value) with
    // nspikes_ref >= target. nspikes is monotone nondecreasing in x.
    unsigned lo = 0u, hi = 0x7F7FFFFFu;  // [0, FLT_MAX]
    while (lo < hi) {
        unsigned mid = lo + ((hi - lo) >> 1);
        if (nspikes_ref(__uint_as_float(mid), s) >= target) hi = mid;
        else lo = mid + 1u;
    }

    float qs = 0.25f * s;
    ((float*)&g_X)[k] = __uint_as_float(hi);
    ((float*)&g_V)[k] = (float)target * qs;
}

__device__ __forceinline__ float lif_sel(float x, float4 X, float4 V) {
    float r = 0.0f;
    r = (x >= X.x) ? V.x : r;
    r = (x >= X.y) ? V.y : r;
    r = (x >= X.z) ? V.z : r;
    r = (x >= X.w) ? V.w : r;
    return r;
}

__global__ void __launch_bounds__(256)
lif_main_kernel(const float4* __restrict__ x, float4* __restrict__ out, int n4) {
    int i = blockIdx.x * blockDim.x + threadIdx.x;
    if (i >= n4) return;

    float4 X = g_X;  // broadcast loads, L1-resident after first wave
    float4 V = g_V;

    float4 xv = x[i];
    float4 r;
    r.x = lif_sel(xv.x, X, V);
    r.y = lif_sel(xv.y, X, V);
    r.z = lif_sel(xv.z, X, V);
    r.w = lif_sel(xv.w, X, V);
    out[i] = r;
}

extern "C" void kernel_launch(void* const* d_in, const int* in_sizes, int n_in,
                              void* d_out, int out_size) {
    const float* x     = (const float*)d_in[0];
    const float* scale = (const float*)d_in[1];
    float* out = (float*)d_out;

    int n  = out_size;   // 4096*8192, divisible by 4
    int n4 = n >> 2;

    lif_setup_kernel<<<1, 4>>>(scale);

    const int threads = 256;
    int blocks = (n4 + threads - 1) / threads;
    lif_main_kernel<<<blocks, threads>>>((const float4*)x, (float4*)out, n4);
}

// round 3
// speedup vs baseline: 1.4716x; 1.0368x over previous
#include <cuda_runtime.h>
#include <cuda_bf16.h>

// LIFActivation as a step function of x (see R2). n_spikes(x) is monotone in
// x for fixed scale, with four float thresholds X1..X4. Setup kernel finds
// each Xk by a warp-parallel 33-ary search over float bit-space, probing with
// the EXACT reference fp32 sequence (__fdiv_rn + sequential adds +
// subtractive reset). Main kernel: out = select chain, 4 independent float4
// streams per thread for MLP.

__device__ float4 g_X;  // thresholds for n>=1..4 (+inf if unreachable)
__device__ float4 g_V;  // output values for n=1..4

__device__ __forceinline__ int nspikes_ref(float x, float s) {
    float c = __fdiv_rn(fmaxf(x, 0.0f), s);  // IEEE RN div, exact ref semantics
    float v = 0.0f;
    int n = 0;
#pragma unroll
    for (int t = 0; t < 4; ++t) {
        v += c;
        if (v >= 1.0f) {  // H(v - 1) == 1  <=>  v >= 1
            v -= 1.0f;
            n += 1;
        }
    }
    return n;
}

// 4 warps, warp k finds the smallest nonnegative float bit-pattern u with
// nspikes_ref(u) >= k+1. 33-ary search: 32 probes per iteration, range/33
// per step -> 7 iterations over [0, FLT_MAX].
__global__ void lif_setup_kernel(const float* __restrict__ scale_ptr) {
    int warp = threadIdx.x >> 5;
    int lane = threadIdx.x & 31;
    if (warp >= 4) return;

    float s = fmaxf(*scale_ptr, 1e-12f);
    int target = warp + 1;

    unsigned lo = 0u, hi = 0x7F7FFFFFu;  // [0, FLT_MAX] as bits == as values
    bool feasible = nspikes_ref(__uint_as_float(hi), s) >= target;

    if (feasible) {
        while (lo < hi) {
            unsigned long long range = (unsigned long long)(hi - lo);
            unsigned p = lo + (unsigned)((range * (unsigned long long)(lane + 1)) / 33ull);
            bool sat = nspikes_ref(__uint_as_float(p), s) >= target;
            unsigned mask = __ballot_sync(0xFFFFFFFFu, sat);
            if (mask == 0u) {
                unsigned p31 = __shfl_sync(0xFFFFFFFFu, p, 31);
                lo = p31 + 1u;            // all probes below threshold
            } else {
                int j = __ffs(mask) - 1;  // first satisfying lane (monotone)
                unsigned pj = __shfl_sync(0xFFFFFFFFu, p, j);
                hi = pj;
                if (j > 0) {
                    unsigned pm = __shfl_sync(0xFFFFFFFFu, p, j - 1);
                    lo = pm + 1u;         // p_{j-1} < p_j and unsat (see monotonicity)
                }
            }
        }
    }

    if (lane == 0) {
        float X = feasible ? __uint_as_float(lo) : __int_as_float(0x7F800000);
        float qs = 0.25f * s;
        ((float*)&g_X)[warp] = X;
        ((float*)&g_V)[warp] = (float)target * qs;
    }
}

__device__ __forceinline__ float lif_sel(float x, float4 X, float4 V) {
    float r = 0.0f;
    r = (x >= X.x) ? V.x : r;
    r = (x >= X.y) ? V.y : r;
    r = (x >= X.z) ? V.z : r;
    r = (x >= X.w) ? V.w : r;
    return r;
}

__device__ __forceinline__ float4 lif_sel4(float4 xv, float4 X, float4 V) {
    float4 r;
    r.x = lif_sel(xv.x, X, V);
    r.y = lif_sel(xv.y, X, V);
    r.z = lif_sel(xv.z, X, V);
    r.w = lif_sel(xv.w, X, V);
    return r;
}

// 4 independent float4 streams per thread (front-batched loads, MLP=4).
__global__ void __launch_bounds__(256)
lif_main_kernel(const float4* __restrict__ x, float4* __restrict__ out,
                int n4, int quarter) {
    int i = blockIdx.x * blockDim.x + threadIdx.x;

    int i0 = i;
    int i1 = i + quarter;
    int i2 = i + 2 * quarter;
    int i3 = i + 3 * quarter;

    bool b0 = i0 < n4, b1 = i1 < n4, b2 = i2 < n4, b3 = i3 < n4;

    float4 a0, a1, a2, a3;
    if (b0) a0 = x[i0];
    if (b1) a1 = x[i1];
    if (b2) a2 = x[i2];
    if (b3) a3 = x[i3];

    float4 X = g_X;
    float4 V = g_V;

    if (b0) out[i0] = lif_sel4(a0, X, V);
    if (b1) out[i1] = lif_sel4(a1, X, V);
    if (b2) out[i2] = lif_sel4(a2, X, V);
    if (b3) out[i3] = lif_sel4(a3, X, V);
}

extern "C" void kernel_launch(void* const* d_in, const int* in_sizes, int n_in,
                              void* d_out, int out_size) {
    const float* x     = (const float*)d_in[0];
    const float* scale = (const float*)d_in[1];
    float* out = (float*)d_out;

    int n  = out_size;       // 4096*8192, divisible by 16
    int n4 = n >> 2;         // float4 count
    int quarter = (n4 + 3) >> 2;

    lif_setup_kernel<<<1, 128>>>(scale);

    const int threads = 256;
    int blocks = (quarter + threads - 1) / threads;
    lif_main_kernel<<<blocks, threads>>>((const float4*)x, (float4*)out, n4, quarter);
}